// round 4
// baseline (speedup 1.0000x reference)
#include <cuda_runtime.h>
#include <stdint.h>

// Viterbi HMM decode: B=512, T=4096, S=16. Output written as FLOAT32
// (state index as float) — the exact-1.0 rel_err signature of rounds 1-2
// indicates the harness compares a float32 output buffer.
//
// One warp per batch. Lanes 0-15 / 16-31 mirror the same batch (width-16
// shuffles), ballot low-16 bits carry psi nibble bit-planes, 8 B/step in
// static shared memory. Backtrack in shared memory.
//
// fp32 ops replicate the XLA reference bitwise: logf == libdevice __nv_logf
// (what jnp.log lowers to), __fmul_rn/__fadd_rn block FMA contraction,
// sequential ascending row-sum, exact fmaxf tree, first-occurrence argmax.

#define T_LEN 4096
#define NSTEPS (T_LEN - 1)   // 4095 psi entries

__global__ void __launch_bounds__(32)
hmm_viterbi_kernel(const float* __restrict__ inputs,
                   const float* __restrict__ hmm,
                   float* __restrict__ out)
{
    __shared__ uint2 psi[NSTEPS];            // 32760 B: {b0|b1<<16, b2|b3<<16}
    __shared__ unsigned char path[T_LEN];    // 4096 B

    const int lane = threadIdx.x;
    const int j    = lane & 15;              // state index (halves mirror)
    const int b    = blockIdx.x;             // one batch per block
    const float* xrow = inputs + b * T_LEN;
    const float* trans = hmm;                // unit 0 only

    // ---- log_A[i][j] = log(trans[i][j]) - log(rowsum[i]);  log_pi = log_A[0] ----
    float s = 0.0f;
    #pragma unroll
    for (int k = 0; k < 16; k++) s = __fadd_rn(s, trans[j * 16 + k]);
    float ls = logf(s);                      // __nv_logf: bitwise == XLA's log
    float A[16];
    #pragma unroll
    for (int i = 0; i < 16; i++) {
        float lt  = logf(trans[i * 16 + j]);
        float lsi = __shfl_sync(0xFFFFFFFFu, ls, i, 16);
        A[i] = __fsub_rn(lt, lsi);
    }

    const float C_NH = -0.9189385332046727f; // -0.5*log(2*pi) in fp32

    // ---- delta0 = log_pi[j] + emit(x0) ----
    float x0 = xrow[0];
    float delta = __fadd_rn(A[0],
                  __fadd_rn(__fmul_rn(__fmul_rn(-0.5f, x0), x0), C_NH));

    // ---- forward pass: t = 1 .. T-1 ----
    float xc = xrow[1];
    for (int t = 1; t < T_LEN; t++) {
        float xn = 0.0f;
        if (t + 1 < T_LEN) xn = xrow[t + 1];   // prefetch, off the delta chain

        float e = __fadd_rn(__fmul_rn(__fmul_rn(-0.5f, xc), xc), C_NH);

        // candidates c[i] = delta[i] + A[i][j]
        float c[16];
        #pragma unroll
        for (int i = 0; i < 16; i++) {
            float d = __shfl_sync(0xFFFFFFFFu, delta, i, 16);
            c[i] = __fadd_rn(d, A[i]);
        }

        // max + first-occurrence argmax (left-preference on exact ties)
        float v[8]; int id[8];
        #pragma unroll
        for (int q = 0; q < 8; q++) {
            bool p = c[2*q] >= c[2*q+1];
            v[q]  = fmaxf(c[2*q], c[2*q+1]);
            id[q] = p ? (2*q) : (2*q + 1);
        }
        #pragma unroll
        for (int q = 0; q < 4; q++) {
            bool p = v[2*q] >= v[2*q+1];
            v[q]  = fmaxf(v[2*q], v[2*q+1]);
            id[q] = p ? id[2*q] : id[2*q+1];
        }
        #pragma unroll
        for (int q = 0; q < 2; q++) {
            bool p = v[2*q] >= v[2*q+1];
            v[q]  = fmaxf(v[2*q], v[2*q+1]);
            id[q] = p ? id[2*q] : id[2*q+1];
        }
        bool p0 = v[0] >= v[1];
        float m = fmaxf(v[0], v[1]);
        int arg = p0 ? id[0] : id[1];

        delta = __fadd_rn(m, e);

        // psi bit-planes: bit (lane&15) of each ballot low half = arg bit
        unsigned b0 = __ballot_sync(0xFFFFFFFFu, (arg & 1) != 0);
        unsigned b1 = __ballot_sync(0xFFFFFFFFu, (arg & 2) != 0);
        unsigned b2 = __ballot_sync(0xFFFFFFFFu, (arg & 4) != 0);
        unsigned b3 = __ballot_sync(0xFFFFFFFFu, (arg & 8) != 0);
        if (lane == 0)
            psi[t - 1] = make_uint2((b0 & 0xFFFFu) | (b1 << 16),
                                    (b2 & 0xFFFFu) | (b3 << 16));
        xc = xn;
    }

    __syncwarp();

    // ---- zT = argmax(deltaT), first occurrence, width-16 butterfly ----
    float v = delta; int zi = j;
    #pragma unroll
    for (int o = 8; o > 0; o >>= 1) {
        float v2 = __shfl_xor_sync(0xFFFFFFFFu, v, o, 16);
        int   i2 = __shfl_xor_sync(0xFFFFFFFFu, zi, o, 16);
        if (v2 > v || (v2 == v && i2 < zi)) { v = v2; zi = i2; }
    }
    int z = zi;
    path[T_LEN - 1] = (unsigned char)z;   // identical writes from all lanes

    // ---- backtrack (all lanes identical; benign identical writes) ----
    for (int k = NSTEPS - 1; k >= 0; k--) {
        uint2 p = psi[k];
        int bb0 = (p.x >> z) & 1;
        int bb1 = (p.x >> (z + 16)) & 1;
        int bb2 = (p.y >> z) & 1;
        int bb3 = (p.y >> (z + 16)) & 1;
        z = bb0 | (bb1 << 1) | (bb2 << 2) | (bb3 << 3);
        path[k] = (unsigned char)z;
    }
    __syncwarp();

    // ---- write output row as FLOAT32, fully coalesced ----
    float* orow = out + b * T_LEN;
    #pragma unroll 4
    for (int t = lane; t < T_LEN; t += 32) orow[t] = (float)path[t];
}

extern "C" void kernel_launch(void* const* d_in, const int* in_sizes, int n_in,
                              void* d_out, int out_size)
{
    // hmm_params (16384 elems) is the smaller buffer; robust to ordering.
    const float* inputs;
    const float* hmm;
    if (in_sizes[0] < in_sizes[1]) {
        hmm    = (const float*)d_in[0];
        inputs = (const float*)d_in[1];
    } else {
        inputs = (const float*)d_in[0];
        hmm    = (const float*)d_in[1];
    }
    hmm_viterbi_kernel<<<512, 32>>>(inputs, hmm, (float*)d_out);
}

// round 5
// speedup vs baseline: 1.4110x; 1.4110x over previous
#include <cuda_runtime.h>
#include <stdint.h>

// Viterbi HMM decode: B=512, T=4096, S=16.  Output = float32 path.
//
// R5 changes vs R4 (635us):
//  - 128 CTAs x 4 warps (1 batch/warp): warps spread across all 4 SMSPs
//    (SMSP = wid%4; R4's 1-warp CTAs all piled onto SMSP 0).
//  - psi stored as byte-map in __device__ global (16 B/step coalesced STG
//    from lanes 0-15) instead of ballot bit-planes (-12 instrs/step).
//  - backtrack stages 256-step tiles into smem, serial chase is LDS-latency.
//  - emission inputs prefetched 8 steps ahead (covers DRAM on cold lines).
//
// fp32 op order is bit-identical to the passing R4 kernel: logf (libdevice
// __nv_logf, == XLA), __fmul_rn/__fadd_rn (no FMA contraction), exact fmaxf
// tree, first-occurrence argmax via left-preference.

#define T_LEN  4096
#define NSTEPS 4095
#define TILE   256
#define B_TOT  512

// padded to T_LEN steps so the last tile's 256-row load stays in bounds
__device__ unsigned char g_psi[B_TOT][T_LEN][16];   // 32 MB scratch

__global__ void __launch_bounds__(128)
hmm_viterbi_kernel(const float* __restrict__ inputs,
                   const float* __restrict__ hmm,
                   float* __restrict__ out)
{
    __shared__ unsigned char s_tile[4][TILE * 16];   // 16 KB
    __shared__ unsigned char s_path[4][T_LEN];       // 16 KB

    const int warp = threadIdx.x >> 5;
    const int lane = threadIdx.x & 31;
    const int j    = lane & 15;               // state (halves mirror)
    const int b    = blockIdx.x * 4 + warp;   // one batch per warp
    const float* xrow  = inputs + b * T_LEN;
    const float* trans = hmm;                 // unit 0 only

    // ---- log_A[i][j] = log(trans[i][j]) - log(rowsum[i]); log_pi = log_A[0] ----
    float s = 0.0f;
    #pragma unroll
    for (int k = 0; k < 16; k++) s = __fadd_rn(s, trans[j * 16 + k]);
    float ls = logf(s);
    float A[16];
    #pragma unroll
    for (int i = 0; i < 16; i++) {
        float lt  = logf(trans[i * 16 + j]);
        float lsi = __shfl_sync(0xFFFFFFFFu, ls, i, 16);
        A[i] = __fsub_rn(lt, lsi);
    }

    const float C_NH = -0.9189385332046727f;  // -0.5*log(2*pi) fp32

    // ---- delta0 ----
    float x0 = xrow[0];
    float delta = __fadd_rn(A[0],
                  __fadd_rn(__fmul_rn(__fmul_rn(-0.5f, x0), x0), C_NH));

    unsigned char* psi_b = &g_psi[b][0][0];
    const bool store_lane = (lane < 16);

    // ---- one Viterbi step (bit-identical to R4) ----
    auto do_step = [&](float x, int kidx) {
        float e = __fadd_rn(__fmul_rn(__fmul_rn(-0.5f, x), x), C_NH);
        float c[16];
        #pragma unroll
        for (int i = 0; i < 16; i++) {
            float d = __shfl_sync(0xFFFFFFFFu, delta, i, 16);
            c[i] = __fadd_rn(d, A[i]);
        }
        float v[8]; int id[8];
        #pragma unroll
        for (int q = 0; q < 8; q++) {
            bool p = c[2*q] >= c[2*q+1];
            v[q]  = fmaxf(c[2*q], c[2*q+1]);
            id[q] = p ? (2*q) : (2*q + 1);
        }
        #pragma unroll
        for (int q = 0; q < 4; q++) {
            bool p = v[2*q] >= v[2*q+1];
            v[q]  = fmaxf(v[2*q], v[2*q+1]);
            id[q] = p ? id[2*q] : id[2*q+1];
        }
        #pragma unroll
        for (int q = 0; q < 2; q++) {
            bool p = v[2*q] >= v[2*q+1];
            v[q]  = fmaxf(v[2*q], v[2*q+1]);
            id[q] = p ? id[2*q] : id[2*q+1];
        }
        bool p0 = v[0] >= v[1];
        float m = fmaxf(v[0], v[1]);
        int arg = p0 ? id[0] : id[1];

        delta = __fadd_rn(m, e);

        // coalesced 16-byte psi store (lanes 0-15), off the delta chain
        if (store_lane) psi_b[kidx * 16 + j] = (unsigned char)arg;
    };

    // ---- forward: 4095 steps = 511 blocks of 8 + 7 tail, prefetch 8 ahead ----
    float xs[8];
    #pragma unroll
    for (int k = 0; k < 8; k++) xs[k] = __ldg(xrow + 1 + k);
    int t = 1;
    for (int blk = 0; blk < 511; blk++) {
        float xn[8];
        #pragma unroll
        for (int k = 0; k < 8; k++) {
            int nt = t + 8 + k;
            nt = nt < T_LEN ? nt : T_LEN - 1;   // clamp (value unused at tail)
            xn[k] = __ldg(xrow + nt);
        }
        #pragma unroll
        for (int k = 0; k < 8; k++) do_step(xs[k], t - 1 + k);
        #pragma unroll
        for (int k = 0; k < 8; k++) xs[k] = xn[k];
        t += 8;
    }
    #pragma unroll
    for (int k = 0; k < 7; k++) do_step(xs[k], t - 1 + k);   // t = 4089..4095

    __syncwarp();

    // ---- zT = argmax(deltaT), first occurrence, width-16 butterfly ----
    float v = delta; int zi = j;
    #pragma unroll
    for (int o = 8; o > 0; o >>= 1) {
        float v2 = __shfl_xor_sync(0xFFFFFFFFu, v, o, 16);
        int   i2 = __shfl_xor_sync(0xFFFFFFFFu, zi, o, 16);
        if (v2 > v || (v2 == v && i2 < zi)) { v = v2; zi = i2; }
    }
    int z = zi;
    if (lane == 0) s_path[warp][T_LEN - 1] = (unsigned char)z;

    // ---- backtrack: 16 tiles of 256 steps, staged through smem ----
    for (int tile = 15; tile >= 0; tile--) {
        const int base = tile * TILE;   // psi steps [base, base+TILE)
        // cooperative stage: 256 rows x 16 B = 4 KB (row T_LEN-1 is padding)
        const uint4* src = reinterpret_cast<const uint4*>(psi_b + base * 16);
        uint4* dst = reinterpret_cast<uint4*>(s_tile[warp]);
        #pragma unroll
        for (int i = 0; i < 8; i++) dst[lane + 32 * i] = src[lane + 32 * i];
        __syncwarp();

        int kstart = (tile == 15) ? (NSTEPS - 1 - base) : (TILE - 1);
        for (int k = kstart; k >= 0; k--) {
            z = s_tile[warp][k * 16 + z];
            if (lane == 0) s_path[warp][base + k] = (unsigned char)z;
        }
        __syncwarp();
    }

    // ---- write output row as float32, coalesced ----
    float* orow = out + b * T_LEN;
    #pragma unroll 4
    for (int tt = lane; tt < T_LEN; tt += 32)
        orow[tt] = (float)s_path[warp][tt];
}

extern "C" void kernel_launch(void* const* d_in, const int* in_sizes, int n_in,
                              void* d_out, int out_size)
{
    const float* inputs;
    const float* hmm;
    if (in_sizes[0] < in_sizes[1]) {
        hmm    = (const float*)d_in[0];
        inputs = (const float*)d_in[1];
    } else {
        inputs = (const float*)d_in[0];
        hmm    = (const float*)d_in[1];
    }
    hmm_viterbi_kernel<<<128, 128>>>(inputs, hmm, (float*)d_out);
}

// round 6
// speedup vs baseline: 1.6217x; 1.1493x over previous
#include <cuda_runtime.h>
#include <stdint.h>

// Viterbi HMM decode: B=512, T=4096, S=16.  Output = float32 path.
//
// R6 vs R5 (450us):
//  K1 forward: split-half reduction. Half h (lanes 16h..16h+15) reduces over
//    predecessors i in [8h, 8h+8): 8 shuffles + 8 adds + 7-node tree, then one
//    shfl_xor(16) merge. Max value is exact (fmaxf), merge tie-break prefers
//    half 0 => global first-occurrence argmax => bit-identical to R4/R5.
//  K2 backtrack chase: one warp per (batch, 256-step tile); 16 lanes chase all
//    16 candidate end states through the smem-staged tile, recording candidate
//    paths + the tile's end->start map. Serial depth 256 instead of 4096.
//  K3 compose + emit: per batch, compose 16 tile maps to find each tile's true
//    end state, then emit the chosen candidate path as float32.

#define T_LEN  4096
#define NSTEPS 4095
#define TILE   256
#define NTILE  16
#define B_TOT  512

__device__ unsigned char g_psi [B_TOT][T_LEN][16];          // 32 MB
__device__ unsigned char g_cand[B_TOT][NTILE][TILE][16];    // 32 MB
__device__ unsigned char g_map [B_TOT][NTILE][16];          // 128 KB
__device__ int           g_zT  [B_TOT];

// ---------------- K1: forward pass ----------------
__global__ void __launch_bounds__(128)
hmm_forward_kernel(const float* __restrict__ inputs,
                   const float* __restrict__ hmm)
{
    const int warp = threadIdx.x >> 5;
    const int lane = threadIdx.x & 31;
    const int j    = lane & 15;               // state (halves mirror)
    const int i0   = (lane & 16) >> 1;        // 0 or 8: this half's i-range base
    const int b    = blockIdx.x * 4 + warp;
    const float* xrow  = inputs + b * T_LEN;
    const float* trans = hmm;                 // unit 0 only

    // ---- log_A for this half's 8 rows; log_pi[j] separately ----
    float s = 0.0f;
    #pragma unroll
    for (int k = 0; k < 16; k++) s = __fadd_rn(s, trans[j * 16 + k]);
    float ls = logf(s);                       // lane j: log(rowsum[j])
    float Ah[8];
    #pragma unroll
    for (int q = 0; q < 8; q++) {
        int i = i0 + q;
        float lt  = logf(trans[i * 16 + j]);
        float lsi = __shfl_sync(0xFFFFFFFFu, ls, i, 16);
        Ah[q] = __fsub_rn(lt, lsi);
    }
    float log_pi = __fsub_rn(logf(trans[j]), __shfl_sync(0xFFFFFFFFu, ls, 0, 16));

    const float C_NH = -0.9189385332046727f;  // -0.5*log(2*pi) fp32

    float x0 = xrow[0];
    float delta = __fadd_rn(log_pi,
                  __fadd_rn(__fmul_rn(__fmul_rn(-0.5f, x0), x0), C_NH));

    unsigned char* psi_b = &g_psi[b][0][0];
    const bool store_lane = (lane < 16);
    const bool half0 = (i0 == 0);

    auto do_step = [&](float x, int kidx) {
        float e = __fadd_rn(__fmul_rn(__fmul_rn(-0.5f, x), x), C_NH);
        // this half's 8 candidates: c[q] = delta[i0+q] + A[i0+q][j]
        float c[8];
        #pragma unroll
        for (int q = 0; q < 8; q++) {
            float d = __shfl_sync(0xFFFFFFFFu, delta, i0 + q, 16);
            c[q] = __fadd_rn(d, Ah[q]);
        }
        // 8-way max + first-occurrence argmax (local indices)
        float v4[4]; int id4[4];
        #pragma unroll
        for (int q = 0; q < 4; q++) {
            bool p = c[2*q] >= c[2*q+1];
            v4[q]  = fmaxf(c[2*q], c[2*q+1]);
            id4[q] = p ? (2*q) : (2*q + 1);
        }
        float v2[2]; int id2[2];
        #pragma unroll
        for (int q = 0; q < 2; q++) {
            bool p = v4[2*q] >= v4[2*q+1];
            v2[q]  = fmaxf(v4[2*q], v4[2*q+1]);
            id2[q] = p ? id4[2*q] : id4[2*q+1];
        }
        bool pl = v2[0] >= v2[1];
        float vh = fmaxf(v2[0], v2[1]);
        int argh = i0 + (pl ? id2[0] : id2[1]);
        // cross-half merge (global tie-break: lower index wins = half 0 on tie)
        float vo = __shfl_xor_sync(0xFFFFFFFFu, vh, 16);
        int   ao = __shfl_xor_sync(0xFFFFFFFFu, argh, 16);
        bool takeMine = half0 ? (vh >= vo) : (vh > vo);
        float m = fmaxf(vh, vo);
        int arg = takeMine ? argh : ao;

        delta = __fadd_rn(m, e);
        if (store_lane) psi_b[kidx * 16 + j] = (unsigned char)arg;
    };

    // forward: 511 blocks of 8 steps + 7 tail, input prefetched 8 ahead
    float xs[8];
    #pragma unroll
    for (int k = 0; k < 8; k++) xs[k] = __ldg(xrow + 1 + k);
    int t = 1;
    for (int blk = 0; blk < 511; blk++) {
        float xn[8];
        #pragma unroll
        for (int k = 0; k < 8; k++) {
            int nt = t + 8 + k;
            nt = nt < T_LEN ? nt : T_LEN - 1;
            xn[k] = __ldg(xrow + nt);
        }
        #pragma unroll
        for (int k = 0; k < 8; k++) do_step(xs[k], t - 1 + k);
        #pragma unroll
        for (int k = 0; k < 8; k++) xs[k] = xn[k];
        t += 8;
    }
    #pragma unroll
    for (int k = 0; k < 7; k++) do_step(xs[k], t - 1 + k);   // t = 4089..4095

    __syncwarp();

    // zT = argmax(deltaT), first occurrence (both halves hold full delta)
    float v = delta; int zi = j;
    #pragma unroll
    for (int o = 8; o > 0; o >>= 1) {
        float v2 = __shfl_xor_sync(0xFFFFFFFFu, v, o, 16);
        int   i2 = __shfl_xor_sync(0xFFFFFFFFu, zi, o, 16);
        if (v2 > v || (v2 == v && i2 < zi)) { v = v2; zi = i2; }
    }
    if (lane == 0) g_zT[b] = zi;
}

// ---------------- K2: per-tile candidate chase ----------------
__global__ void __launch_bounds__(128)
hmm_chase_kernel()
{
    __shared__ unsigned char s_psi[4][TILE * 16];   // 16 KB

    const int warp = threadIdx.x >> 5;
    const int lane = threadIdx.x & 31;
    const int b    = blockIdx.x;
    const int tile = blockIdx.y * 4 + warp;

    // stage this tile's psi rows (4 KB) into smem, coalesced
    const uint4* src = reinterpret_cast<const uint4*>(&g_psi[b][tile * TILE][0]);
    uint4* dst = reinterpret_cast<uint4*>(s_psi[warp]);
    #pragma unroll
    for (int i = 0; i < 8; i++) dst[lane + 32 * i] = src[lane + 32 * i];
    __syncwarp();

    // chase all 16 candidate end states (lanes 16-31 mirror, stores masked)
    int z = lane & 15;
    const int kmax = (tile == NTILE - 1) ? (TILE - 2) : (TILE - 1);  // psi idx <= 4094
    const bool st = (lane < 16);
    unsigned char* cand = &g_cand[b][tile][0][0];
    for (int k = kmax; k >= 0; k--) {
        z = s_psi[warp][k * 16 + z];
        if (st) cand[k * 16 + lane] = (unsigned char)z;
    }
    if (st) g_map[b][tile][lane] = (unsigned char)z;
}

// ---------------- K3: compose maps + emit path ----------------
__global__ void __launch_bounds__(128)
hmm_emit_kernel(float* __restrict__ out)
{
    __shared__ unsigned char e_tile[NTILE];
    const int b = blockIdx.x;

    if (threadIdx.x == 0) {
        int z = g_zT[b];
        e_tile[NTILE - 1] = (unsigned char)z;
        #pragma unroll
        for (int tau = NTILE - 1; tau >= 1; tau--) {
            z = g_map[b][tau][z];
            e_tile[tau - 1] = (unsigned char)z;
        }
    }
    __syncthreads();

    float* orow = out + b * T_LEN;
    for (int t = threadIdx.x; t < NSTEPS; t += 128) {
        int tau = t >> 8, k = t & (TILE - 1);
        orow[t] = (float)g_cand[b][tau][k][e_tile[tau]];
    }
    if (threadIdx.x == 0) orow[T_LEN - 1] = (float)g_zT[b];
}

extern "C" void kernel_launch(void* const* d_in, const int* in_sizes, int n_in,
                              void* d_out, int out_size)
{
    const float* inputs;
    const float* hmm;
    if (in_sizes[0] < in_sizes[1]) {
        hmm    = (const float*)d_in[0];
        inputs = (const float*)d_in[1];
    } else {
        inputs = (const float*)d_in[0];
        hmm    = (const float*)d_in[1];
    }
    hmm_forward_kernel<<<128, 128>>>(inputs, hmm);
    hmm_chase_kernel<<<dim3(B_TOT, 4), 128>>>();
    hmm_emit_kernel<<<B_TOT, 128>>>((float*)d_out);
}